// round 2
// baseline (speedup 1.0000x reference)
#include <cuda_runtime.h>
#include <cuda_bf16.h>
#include <math.h>

#define N_NODES   50000
#define F         128
#define NCLS      2

// Scratch (device globals: allocation-free)
__device__ float g_agg[N_NODES * F];   // 25.6 MB
__device__ float g_deg[N_NODES];
__device__ int   g_is64;

// ---------------------------------------------------------------------------
// 0) index dtype probe: int64 positive values have all-odd 32b words == 0
// ---------------------------------------------------------------------------
__global__ void detect_kernel(const int* __restrict__ src,
                              const int* __restrict__ dst, int E) {
    if (threadIdx.x == 0 && blockIdx.x == 0) {
        int nz = 0;
        int lim = 2 * E < 128 ? 2 * E : 128;
        for (int i = 1; i < lim; i += 2) nz |= (src[i] | dst[i]);
        g_is64 = (nz == 0) ? 1 : 0;
    }
}

// ---------------------------------------------------------------------------
// 1) zero scratch
// ---------------------------------------------------------------------------
__global__ void zero_kernel() {
    int tid = blockIdx.x * blockDim.x + threadIdx.x;
    int stride = gridDim.x * blockDim.x;
    const int NV4 = (N_NODES * F) / 4;
    float4* agg4 = reinterpret_cast<float4*>(g_agg);
    for (int i = tid; i < NV4; i += stride)
        agg4[i] = make_float4(0.f, 0.f, 0.f, 0.f);
    for (int i = tid; i < N_NODES; i += stride)
        g_deg[i] = 0.f;
}

// ---------------------------------------------------------------------------
// 2) edge scatter: one warp per edge, vectorized f32x4 reduction into L2
// ---------------------------------------------------------------------------
__global__ void scatter_kernel(const float* __restrict__ feat,
                               const void* __restrict__ srcv,
                               const void* __restrict__ dstv,
                               int E) {
    int warp = (blockIdx.x * blockDim.x + threadIdx.x) >> 5;
    int lane = threadIdx.x & 31;
    if (warp >= E) return;

    long long s, d;
    if (g_is64) {
        s = reinterpret_cast<const long long*>(srcv)[warp];
        d = reinterpret_cast<const long long*>(dstv)[warp];
    } else {
        s = reinterpret_cast<const int*>(srcv)[warp];
        d = reinterpret_cast<const int*>(dstv)[warp];
    }
    if (s < 0 || s >= N_NODES || d < 0 || d >= N_NODES) return;

    float4 v = *reinterpret_cast<const float4*>(&feat[(size_t)s * F + lane * 4]);
    float* addr = &g_agg[(size_t)d * F + lane * 4];
    asm volatile("red.global.add.v4.f32 [%0], {%1, %2, %3, %4};"
                 :: "l"(addr), "f"(v.x), "f"(v.y), "f"(v.z), "f"(v.w)
                 : "memory");
    if (lane == 0) atomicAdd(&g_deg[d], 1.0f);
}

// ---------------------------------------------------------------------------
// 3) fused: h = relu(X*Ws^T + (A/deg)*Wn^T + bn); out = sigmoid(h*Wfc^T + bfc)
// ---------------------------------------------------------------------------
#define GEMM_THREADS 256
#define GEMM_WARPS   (GEMM_THREADS / 32)
#define NODES_PER_WARP 4
#define SMEM_FLOATS (16384 + 16384 + GEMM_WARPS * NODES_PER_WARP * F * 2)
#define SMEM_BYTES  (SMEM_FLOATS * 4)

__global__ void __launch_bounds__(GEMM_THREADS, 1)
fused_gemm_kernel(const float* __restrict__ feat,
                  const float* __restrict__ Wself,
                  const float* __restrict__ Wneigh,
                  const float* __restrict__ bneigh,
                  const float* __restrict__ Wfc,
                  const float* __restrict__ bfc,
                  float* __restrict__ out) {
    extern __shared__ float smem[];
    float* Ws = smem;                 // [k*128 + j]
    float* Wn = smem + 16384;
    float* xbuf = smem + 32768;       // per-warp [4][128]
    float* abuf = xbuf + GEMM_WARPS * NODES_PER_WARP * F;

    int tid = threadIdx.x;
    int warpid = tid >> 5;
    int lane = tid & 31;

    // load transposed weights (Wt[k][j] = W[j][k])
    for (int idx = tid; idx < 16384; idx += GEMM_THREADS) {
        int k = idx >> 7, j = idx & 127;
        Ws[idx] = Wself[j * F + k];
        Wn[idx] = Wneigh[j * F + k];
    }
    __syncthreads();

    // per-lane constants for epilogue
    float4 bn = *reinterpret_cast<const float4*>(&bneigh[lane * 4]);
    float4 f0 = *reinterpret_cast<const float4*>(&Wfc[lane * 4]);          // class 0
    float4 f1 = *reinterpret_cast<const float4*>(&Wfc[F + lane * 4]);      // class 1
    float bfc0 = bfc[0], bfc1 = bfc[1];

    float* xsw = xbuf + warpid * NODES_PER_WARP * F;
    float* asw = abuf + warpid * NODES_PER_WARP * F;

    int gwarp = blockIdx.x * GEMM_WARPS + warpid;
    int nwarps = gridDim.x * GEMM_WARPS;

    for (int base = gwarp * NODES_PER_WARP; base < N_NODES;
         base += nwarps * NODES_PER_WARP) {

        // stage 4 node rows (x and a/deg) into shared
        #pragma unroll
        for (int nn = 0; nn < NODES_PER_WARP; nn++) {
            int n = base + nn;
            int nc = (n < N_NODES) ? n : (N_NODES - 1);
            float4 xv = *reinterpret_cast<const float4*>(&feat[(size_t)nc * F + lane * 4]);
            float invd = 1.0f / fmaxf(g_deg[nc], 1.0f);
            float4 av = *reinterpret_cast<const float4*>(&g_agg[(size_t)nc * F + lane * 4]);
            av.x *= invd; av.y *= invd; av.z *= invd; av.w *= invd;
            *reinterpret_cast<float4*>(&xsw[nn * F + lane * 4]) = xv;
            *reinterpret_cast<float4*>(&asw[nn * F + lane * 4]) = av;
        }
        __syncwarp();

        float acc[NODES_PER_WARP][4];
        #pragma unroll
        for (int nn = 0; nn < NODES_PER_WARP; nn++)
            #pragma unroll
            for (int c = 0; c < 4; c++) acc[nn][c] = 0.f;

        #pragma unroll 4
        for (int k4 = 0; k4 < F; k4 += 4) {
            float4 xq[NODES_PER_WARP], aq[NODES_PER_WARP];
            #pragma unroll
            for (int nn = 0; nn < NODES_PER_WARP; nn++) {
                xq[nn] = *reinterpret_cast<float4*>(&xsw[nn * F + k4]);  // broadcast
                aq[nn] = *reinterpret_cast<float4*>(&asw[nn * F + k4]);
            }
            #pragma unroll
            for (int kk = 0; kk < 4; kk++) {
                int k = k4 + kk;
                float4 ws = *reinterpret_cast<float4*>(&Ws[k * F + lane * 4]);
                float4 wn = *reinterpret_cast<float4*>(&Wn[k * F + lane * 4]);
                #pragma unroll
                for (int nn = 0; nn < NODES_PER_WARP; nn++) {
                    float xv = reinterpret_cast<float*>(&xq[nn])[kk];
                    float av = reinterpret_cast<float*>(&aq[nn])[kk];
                    acc[nn][0] += xv * ws.x + av * wn.x;
                    acc[nn][1] += xv * ws.y + av * wn.y;
                    acc[nn][2] += xv * ws.z + av * wn.z;
                    acc[nn][3] += xv * ws.w + av * wn.w;
                }
            }
        }
        __syncwarp();

        // epilogue: relu + 128->2 projection + sigmoid
        #pragma unroll
        for (int nn = 0; nn < NODES_PER_WARP; nn++) {
            int n = base + nn;
            float h0 = fmaxf(acc[nn][0] + bn.x, 0.f);
            float h1 = fmaxf(acc[nn][1] + bn.y, 0.f);
            float h2 = fmaxf(acc[nn][2] + bn.z, 0.f);
            float h3 = fmaxf(acc[nn][3] + bn.w, 0.f);
            float p0 = h0 * f0.x + h1 * f0.y + h2 * f0.z + h3 * f0.w;
            float p1 = h0 * f1.x + h1 * f1.y + h2 * f1.z + h3 * f1.w;
            #pragma unroll
            for (int off = 16; off; off >>= 1) {
                p0 += __shfl_xor_sync(0xffffffffu, p0, off);
                p1 += __shfl_xor_sync(0xffffffffu, p1, off);
            }
            if (lane == 0 && n < N_NODES) {
                float l0 = p0 + bfc0, l1 = p1 + bfc1;
                out[(size_t)n * NCLS + 0] = 1.0f / (1.0f + expf(-l0));
                out[(size_t)n * NCLS + 1] = 1.0f / (1.0f + expf(-l1));
            }
        }
    }
}

// ---------------------------------------------------------------------------
extern "C" void kernel_launch(void* const* d_in, const int* in_sizes, int n_in,
                              void* d_out, int out_size) {
    const float* feat   = (const float*)d_in[0];
    const void*  src    = d_in[1];
    const void*  dst    = d_in[2];
    const float* Wself  = (const float*)d_in[3];
    const float* Wneigh = (const float*)d_in[4];
    const float* bneigh = (const float*)d_in[5];
    const float* Wfc    = (const float*)d_in[6];
    const float* bfc    = (const float*)d_in[7];
    float*       out    = (float*)d_out;
    int E = in_sizes[1];

    cudaFuncSetAttribute(fused_gemm_kernel,
                         cudaFuncAttributeMaxDynamicSharedMemorySize, SMEM_BYTES);

    detect_kernel<<<1, 32>>>((const int*)src, (const int*)dst, E);
    zero_kernel<<<1024, 256>>>();

    int sblocks = (E + 7) / 8;   // 8 edges (warps) per 256-thread block
    scatter_kernel<<<sblocks, 256>>>(feat, src, dst, E);

    fused_gemm_kernel<<<152, GEMM_THREADS, SMEM_BYTES>>>(
        feat, Wself, Wneigh, bneigh, Wfc, bfc, out);
}

// round 4
// speedup vs baseline: 1.6654x; 1.6654x over previous
#include <cuda_runtime.h>
#include <cuda_bf16.h>
#include <math.h>
#include <cstdint>

#define N_NODES 50000
#define F       128
#define NCLS    2
#define N_TILES ((N_NODES + 127) / 128)   // 391

// Scratch (device globals: allocation-free)
__device__ float g_agg[N_NODES * F];   // 25.6 MB
__device__ float g_deg[N_NODES];
__device__ int   g_is64;

// ---------------------------------------------------------------------------
// 0) index dtype probe: int64 positive values have all-odd 32b words == 0
// ---------------------------------------------------------------------------
__global__ void detect_kernel(const int* __restrict__ src,
                              const int* __restrict__ dst, int E) {
    if (threadIdx.x == 0 && blockIdx.x == 0) {
        int nz = 0;
        int lim = 2 * E < 128 ? 2 * E : 128;
        for (int i = 1; i < lim; i += 2) nz |= (src[i] | dst[i]);
        g_is64 = (nz == 0) ? 1 : 0;
    }
}

// ---------------------------------------------------------------------------
// 1) zero scratch
// ---------------------------------------------------------------------------
__global__ void zero_kernel() {
    int tid = blockIdx.x * blockDim.x + threadIdx.x;
    int stride = gridDim.x * blockDim.x;
    const int NV4 = (N_NODES * F) / 4;
    float4* agg4 = reinterpret_cast<float4*>(g_agg);
    for (int i = tid; i < NV4; i += stride)
        agg4[i] = make_float4(0.f, 0.f, 0.f, 0.f);
    for (int i = tid; i < N_NODES; i += stride)
        g_deg[i] = 0.f;
}

// ---------------------------------------------------------------------------
// 2) edge scatter: one warp per edge, vectorized f32x4 reduction into L2
// ---------------------------------------------------------------------------
__global__ void scatter_kernel(const float* __restrict__ feat,
                               const void* __restrict__ srcv,
                               const void* __restrict__ dstv,
                               int E) {
    int warp = (blockIdx.x * blockDim.x + threadIdx.x) >> 5;
    int lane = threadIdx.x & 31;
    if (warp >= E) return;

    long long s, d;
    if (g_is64) {
        s = reinterpret_cast<const long long*>(srcv)[warp];
        d = reinterpret_cast<const long long*>(dstv)[warp];
    } else {
        s = reinterpret_cast<const int*>(srcv)[warp];
        d = reinterpret_cast<const int*>(dstv)[warp];
    }
    if (s < 0 || s >= N_NODES || d < 0 || d >= N_NODES) return;

    float4 v = *reinterpret_cast<const float4*>(&feat[(size_t)s * F + lane * 4]);
    float* addr = &g_agg[(size_t)d * F + lane * 4];
    asm volatile("red.global.add.v4.f32 [%0], {%1, %2, %3, %4};"
                 :: "l"(addr), "f"(v.x), "f"(v.y), "f"(v.z), "f"(v.w)
                 : "memory");
    if (lane == 0) atomicAdd(&g_deg[d], 1.0f);
}

// ---------------------------------------------------------------------------
// 3) tf32 mma.sync GEMM: D[128tile x 128] = [X | Agg/deg] @ [Ws | Wn]^T
//    fused epilogue: bias, relu, 128->2 fc, sigmoid
// ---------------------------------------------------------------------------
// smem layout (bytes)
#define A_PAD    36                      // 32 + 4 floats per A row
#define B_PAD    132                     // 128 + 4 floats per B(k) row
#define OFF_B    0                       // [256][132] u32  = 135168 B
#define OFF_A    135168                  // 2 x [128][36]   =  36864 B
#define OFF_BN   172032                  // 128 f
#define OFF_F0   172544
#define OFF_F1   173056
#define OFF_INVD 173568
#define OFF_PART 174080                  // [128][2][2] f   = 2048 B
#define SMEM_TOTAL 176128

__device__ __forceinline__ uint32_t f2tf(float v) {
    uint32_t r;
    asm("cvt.rna.tf32.f32 %0, %1;" : "=r"(r) : "f"(v));
    return r;
}
__device__ __forceinline__ void mma_tf32(float* c, const uint32_t* a,
                                         const uint32_t* b) {
    asm volatile("mma.sync.aligned.m16n8k8.row.col.f32.tf32.tf32.f32 "
                 "{%0,%1,%2,%3}, {%4,%5,%6,%7}, {%8,%9}, {%0,%1,%2,%3};"
                 : "+f"(c[0]), "+f"(c[1]), "+f"(c[2]), "+f"(c[3])
                 : "r"(a[0]), "r"(a[1]), "r"(a[2]), "r"(a[3]),
                   "r"(b[0]), "r"(b[1]));
}

__global__ void __launch_bounds__(256, 1)
mma_gemm_kernel(const float* __restrict__ feat,
                const float* __restrict__ Wself,
                const float* __restrict__ Wneigh,
                const float* __restrict__ bneigh,
                const float* __restrict__ Wfc,
                const float* __restrict__ bfc,
                float* __restrict__ out) {
    extern __shared__ char smem[];
    uint32_t* Bs   = (uint32_t*)(smem + OFF_B);
    uint32_t* As   = (uint32_t*)(smem + OFF_A);
    float* bn_s    = (float*)(smem + OFF_BN);
    float* f0_s    = (float*)(smem + OFF_F0);
    float* f1_s    = (float*)(smem + OFF_F1);
    float* invd_s  = (float*)(smem + OFF_INVD);
    float* part    = (float*)(smem + OFF_PART);

    const int tid = threadIdx.x;
    const int wid = tid >> 5, lane = tid & 31;
    const int m_idx = wid >> 1;          // 0..3  (rows m_idx*32..+32)
    const int n_idx = wid & 1;           // 0..1  (cols n_idx*64..+64)
    const int groupr = lane >> 2, tcol = lane & 3;

    // --- stage B = [Ws | Wn]^T as [k][n], tf32, once per CTA ---------------
    const float4* Ws4 = (const float4*)Wself;
    const float4* Wn4 = (const float4*)Wneigh;
    for (int t = tid; t < 128 * 64; t += 256) {
        int j  = t & 127;                 // output col n
        int kq = t >> 7;                  // float4 along combined K
        float4 v = (kq < 32) ? Ws4[j * 32 + kq] : Wn4[j * 32 + (kq - 32)];
        int k = kq * 4;
        Bs[(k + 0) * B_PAD + j] = f2tf(v.x);
        Bs[(k + 1) * B_PAD + j] = f2tf(v.y);
        Bs[(k + 2) * B_PAD + j] = f2tf(v.z);
        Bs[(k + 3) * B_PAD + j] = f2tf(v.w);
    }
    if (tid < 128) {
        bn_s[tid] = bneigh[tid];
        f0_s[tid] = Wfc[tid];
        f1_s[tid] = Wfc[128 + tid];
    }

    const float4* feat4 = (const float4*)feat;
    const float4* agg4  = (const float4*)g_agg;
    const float bfc0 = bfc[0], bfc1 = bfc[1];

    for (int tile = blockIdx.x; tile < N_TILES; tile += gridDim.x) {
        // inv-degree for this tile's rows
        if (tid < 128) {
            int node = tile * 128 + tid;
            int nc = node < N_NODES ? node : N_NODES - 1;
            invd_s[tid] = 1.0f / fmaxf(g_deg[nc], 1.0f);
        }

        // A chunk stager (K-chunk of 32 floats, tf32 into padded smem)
        auto stage = [&](int c, int buf) {
            uint32_t* A_ = As + buf * (128 * A_PAD);
            #pragma unroll
            for (int i = 0; i < 4; i++) {
                int idx = tid + i * 256;           // 0..1023
                int row = idx >> 3, q = idx & 7;   // q: float4 within chunk
                int node = tile * 128 + row;
                int nc = node < N_NODES ? node : N_NODES - 1;
                float4 v;
                if (c < 4) {
                    v = feat4[(size_t)nc * 32 + c * 8 + q];
                } else {
                    v = agg4[(size_t)nc * 32 + (c - 4) * 8 + q];
                    float iv = invd_s[row];
                    v.x *= iv; v.y *= iv; v.z *= iv; v.w *= iv;
                }
                uint32_t* p = A_ + row * A_PAD + q * 4;
                p[0] = f2tf(v.x); p[1] = f2tf(v.y);
                p[2] = f2tf(v.z); p[3] = f2tf(v.w);
            }
        };

        float C[2][8][4];
        #pragma unroll
        for (int mt = 0; mt < 2; mt++)
            #pragma unroll
            for (int nt = 0; nt < 8; nt++)
                #pragma unroll
                for (int i = 0; i < 4; i++) C[mt][nt][i] = 0.f;

        stage(0, 0);
        __syncthreads();

        #pragma unroll 1
        for (int c = 0; c < 8; c++) {
            if (c < 7) stage(c + 1, (c + 1) & 1);

            const uint32_t* A_ = As + (c & 1) * (128 * A_PAD);
            const int abase = (m_idx * 32 + groupr) * A_PAD;
            const int bcol  = n_idx * 64 + groupr;
            #pragma unroll
            for (int kk = 0; kk < 4; kk++) {
                const int ka = kk * 8 + tcol;
                uint32_t a[2][4];
                #pragma unroll
                for (int mt = 0; mt < 2; mt++) {
                    int ab = abase + mt * 16 * A_PAD;
                    a[mt][0] = A_[ab + ka];
                    a[mt][1] = A_[ab + 8 * A_PAD + ka];
                    a[mt][2] = A_[ab + ka + 4];
                    a[mt][3] = A_[ab + 8 * A_PAD + ka + 4];
                }
                const int kb = (c * 32 + kk * 8 + tcol) * B_PAD;
                #pragma unroll
                for (int nt = 0; nt < 8; nt++) {
                    uint32_t b[2];
                    b[0] = Bs[kb + bcol + nt * 8];
                    b[1] = Bs[kb + 4 * B_PAD + bcol + nt * 8];
                    mma_tf32(C[0][nt], a[0], b);
                    mma_tf32(C[1][nt], a[1], b);
                }
            }
            __syncthreads();
        }

        // --- epilogue: h = relu(c + bn); p += h * fc; quad-reduce ----------
        float p[2][2][2];   // [mt][rowhalf][cls]
        #pragma unroll
        for (int mt = 0; mt < 2; mt++)
            #pragma unroll
            for (int hh = 0; hh < 2; hh++) { p[mt][hh][0] = 0.f; p[mt][hh][1] = 0.f; }

        #pragma unroll
        for (int nt = 0; nt < 8; nt++) {
            #pragma unroll
            for (int ii = 0; ii < 2; ii++) {
                int col = n_idx * 64 + nt * 8 + 2 * tcol + ii;
                float bnv = bn_s[col], f0v = f0_s[col], f1v = f1_s[col];
                #pragma unroll
                for (int mt = 0; mt < 2; mt++) {
                    #pragma unroll
                    for (int hh = 0; hh < 2; hh++) {
                        float h = fmaxf(C[mt][nt][hh * 2 + ii] + bnv, 0.f);
                        p[mt][hh][0] += h * f0v;
                        p[mt][hh][1] += h * f1v;
                    }
                }
            }
        }
        #pragma unroll
        for (int mt = 0; mt < 2; mt++)
            #pragma unroll
            for (int hh = 0; hh < 2; hh++)
                #pragma unroll
                for (int cl = 0; cl < 2; cl++) {
                    float v = p[mt][hh][cl];
                    v += __shfl_xor_sync(0xffffffffu, v, 1);
                    v += __shfl_xor_sync(0xffffffffu, v, 2);
                    p[mt][hh][cl] = v;
                }
        if (tcol == 0) {
            #pragma unroll
            for (int mt = 0; mt < 2; mt++)
                #pragma unroll
                for (int hh = 0; hh < 2; hh++) {
                    int row = m_idx * 32 + mt * 16 + hh * 8 + groupr;
                    part[row * 4 + n_idx * 2 + 0] = p[mt][hh][0];
                    part[row * 4 + n_idx * 2 + 1] = p[mt][hh][1];
                }
        }
        __syncthreads();
        if (tid < 128) {
            int node = tile * 128 + tid;
            if (node < N_NODES) {
                float l0 = part[tid * 4 + 0] + part[tid * 4 + 2] + bfc0;
                float l1 = part[tid * 4 + 1] + part[tid * 4 + 3] + bfc1;
                float2 o;
                o.x = 1.0f / (1.0f + expf(-l0));
                o.y = 1.0f / (1.0f + expf(-l1));
                *(float2*)&out[(size_t)node * 2] = o;
            }
        }
        __syncthreads();
    }
}

// ---------------------------------------------------------------------------
extern "C" void kernel_launch(void* const* d_in, const int* in_sizes, int n_in,
                              void* d_out, int out_size) {
    const float* feat   = (const float*)d_in[0];
    const void*  src    = d_in[1];
    const void*  dst    = d_in[2];
    const float* Wself  = (const float*)d_in[3];
    const float* Wneigh = (const float*)d_in[4];
    const float* bneigh = (const float*)d_in[5];
    const float* Wfc    = (const float*)d_in[6];
    const float* bfc    = (const float*)d_in[7];
    float*       out    = (float*)d_out;
    int E = in_sizes[1];

    cudaFuncSetAttribute(mma_gemm_kernel,
                         cudaFuncAttributeMaxDynamicSharedMemorySize, SMEM_TOTAL);

    detect_kernel<<<1, 32>>>((const int*)src, (const int*)dst, E);
    zero_kernel<<<1024, 256>>>();

    int sblocks = (E + 7) / 8;   // 8 edges (warps) per 256-thread block
    scatter_kernel<<<sblocks, 256>>>(feat, src, dst, E);

    mma_gemm_kernel<<<148, 256, SMEM_TOTAL>>>(
        feat, Wself, Wneigh, bneigh, Wfc, bfc, out);
}